// round 10
// baseline (speedup 1.0000x reference)
#include <cuda_runtime.h>
#include <cuda_fp16.h>
#include <math.h>

// Problem constants (fixed shapes)
#define Bb 64
#define Vv 100000
#define Ff 200000
#define Ee (6 * Ff)          // 1,200,000 adjacency entries (always even per vertex)
#define VT_STRIDE 192        // per-vertex halves: 3 comps * 64 batches

// -------- device scratch (static; no allocations allowed) --------
__device__ int    g_deg[Vv];
__device__ int    g_rowptr[Vv + 1];
__device__ int    g_cursor[Vv];
__device__ __align__(8) int g_adj[Ee];
__device__ __align__(16) __half g_vT[(size_t)Vv * VT_STRIDE];   // 38.4 MB, layout [v][c][b] fp16
__device__ int    g_blocksums[256];
__device__ float  g_accum;
__device__ int    g_faces64;   // 1 if faces buffer is int64, 0 if int32

// -------- 1) init degrees + detect faces dtype + clear accum --------
__global__ void k_init(const int* __restrict__ faces_w) {
    int idx = blockIdx.x * blockDim.x + threadIdx.x;
    if (idx < Vv) g_deg[idx] = 0;
    if (idx == 0) {
        int nz = 0;
        #pragma unroll
        for (int t = 0; t < 64; t++) nz |= faces_w[2 * t + 1];
        g_faces64 = (nz == 0) ? 1 : 0;
        g_accum = 0.0f;
    }
}

__device__ __forceinline__ void load_face(const int* __restrict__ fw, int f, int w64,
                                          int& i, int& j, int& k) {
    if (w64) {
        i = fw[6 * f + 0];
        j = fw[6 * f + 2];
        k = fw[6 * f + 4];
    } else {
        i = fw[3 * f + 0];
        j = fw[3 * f + 1];
        k = fw[3 * f + 2];
    }
}

// -------- transpose tile worker: verts [B][V][3] f32 -> vT [V][3][B] fp16 --------
#define TP_VT 32
#define TP_NB (Vv / TP_VT)                  // 3125 tiles total
#define TP_SPLIT 1562                       // tiles done inside k_count_tp; rest in k_fill_tp

__device__ __forceinline__ void transpose_tile(const float* __restrict__ verts,
                                               float* sh, int v0) {
    int t = threadIdx.x;                     // 256 threads
    #pragma unroll
    for (int it = 0; it < 24; it++) {
        int l = it * 256 + t;
        int b = l / 96;
        int rem = l - b * 96;
        float val = verts[(size_t)b * (Vv * 3) + (size_t)v0 * 3 + rem];
        sh[rem * 65 + b] = val;              // [rem][b], pad 65 kills bank conflicts
    }
    __syncthreads();

    __half2* out = (__half2*)(g_vT + (size_t)v0 * VT_STRIDE);
    #pragma unroll
    for (int it = 0; it < 12; it++) {
        int o = it * 256 + t;                // half2 index within tile
        int v = o / 96;
        int r = o - v * 96;
        int c = r >> 5;                      // component
        int bp = r & 31;                     // batch pair
        float f0 = sh[(v * 3 + c) * 65 + 2 * bp];
        float f1 = sh[(v * 3 + c) * 65 + 2 * bp + 1];
        out[o] = __floats2half2_rn(f0, f1);
    }
}

// -------- 2) degree count + first half of transpose (heterogeneous grid) --------
#define COUNT_NB ((Ff + 255) / 256)          // 782
__global__ void __launch_bounds__(256) k_count_tp(const int* __restrict__ faces_w,
                                                  const float* __restrict__ verts) {
    __shared__ float sh[TP_VT * 3 * 65];
    if (blockIdx.x < COUNT_NB) {
        int f = blockIdx.x * 256 + threadIdx.x;
        if (f >= Ff) return;
        int w64 = g_faces64;
        int i, j, k;
        load_face(faces_w, f, w64, i, j, k);
        atomicAdd(&g_deg[i], 2);
        atomicAdd(&g_deg[j], 2);
        atomicAdd(&g_deg[k], 2);
    } else {
        transpose_tile(verts, sh, (int)(blockIdx.x - COUNT_NB) * TP_VT);
    }
}

// -------- 3) scan, level 1 (512-wide blocks, warp shuffles) --------
#define SCAN_BS 512
#define SCAN_NB ((Vv + SCAN_BS - 1) / SCAN_BS)   // 196

__global__ void k_scan1() {
    __shared__ int wsum[16];
    int tid = threadIdx.x, lane = tid & 31, w = tid >> 5;
    int gid = blockIdx.x * SCAN_BS + tid;
    int val = (gid < Vv) ? g_deg[gid] : 0;
    int x = val;
    #pragma unroll
    for (int off = 1; off < 32; off <<= 1) {
        int y = __shfl_up_sync(0xFFFFFFFFu, x, off);
        if (lane >= off) x += y;
    }
    if (lane == 31) wsum[w] = x;
    __syncthreads();
    if (w == 0) {
        int s = (lane < 16) ? wsum[lane] : 0;
        #pragma unroll
        for (int off = 1; off < 16; off <<= 1) {
            int y = __shfl_up_sync(0xFFFFFFFFu, s, off);
            if (lane >= off) s += y;
        }
        if (lane < 16) wsum[lane] = s;
    }
    __syncthreads();
    int base = (w > 0) ? wsum[w - 1] : 0;
    int incl = base + x;
    if (gid < Vv) g_rowptr[gid] = incl - val;        // exclusive within block
    if (tid == SCAN_BS - 1) g_blocksums[blockIdx.x] = incl;
}

// -------- 3b) scan finalize --------
__global__ void k_scan3() {
    __shared__ int spre[256];   // exclusive prefix of blocksums
    __shared__ int wsum[8];
    int tid = threadIdx.x, lane = tid & 31, w = tid >> 5;   // 256 threads
    int val = (tid < SCAN_NB) ? g_blocksums[tid] : 0;
    int x = val;
    #pragma unroll
    for (int off = 1; off < 32; off <<= 1) {
        int y = __shfl_up_sync(0xFFFFFFFFu, x, off);
        if (lane >= off) x += y;
    }
    if (lane == 31) wsum[w] = x;
    __syncthreads();
    if (w == 0) {
        int s = (lane < 8) ? wsum[lane] : 0;
        #pragma unroll
        for (int off = 1; off < 8; off <<= 1) {
            int y = __shfl_up_sync(0xFFFFFFFFu, s, off);
            if (lane >= off) s += y;
        }
        if (lane < 8) wsum[lane] = s;
    }
    __syncthreads();
    int base = (w > 0) ? wsum[w - 1] : 0;
    spre[tid] = base + x - val;                       // exclusive blocksum prefix
    __syncthreads();

    int gid = blockIdx.x * blockDim.x + tid;
    if (gid < Vv) {
        int r = g_rowptr[gid] + spre[gid / SCAN_BS];
        g_rowptr[gid] = r;
        g_cursor[gid] = r;
    }
    if (gid == 0) g_rowptr[Vv] = Ee;
}

// -------- 4) CSR fill + second half of transpose (heterogeneous grid) --------
#define FILL_NB ((Ff + 255) / 256)          // 782
__global__ void __launch_bounds__(256) k_fill_tp(const int* __restrict__ faces_w,
                                                 const float* __restrict__ verts) {
    __shared__ float sh[TP_VT * 3 * 65];
    if (blockIdx.x < FILL_NB) {
        int f = blockIdx.x * 256 + threadIdx.x;
        if (f >= Ff) return;
        int w64 = g_faces64;
        int i, j, k;
        load_face(faces_w, f, w64, i, j, k);
        int p;
        p = atomicAdd(&g_cursor[i], 2); g_adj[p] = j; g_adj[p + 1] = k;
        p = atomicAdd(&g_cursor[j], 2); g_adj[p] = i; g_adj[p + 1] = k;
        p = atomicAdd(&g_cursor[k], 2); g_adj[p] = j; g_adj[p + 1] = i;
    } else {
        transpose_tile(verts, sh, (int)(TP_SPLIT + blockIdx.x - FILL_NB) * TP_VT);
    }
}

// -------- 6) gather + norm + reduce (unchanged from R9 winner) --------
#define GATHER_WARPS 8
__global__ void __launch_bounds__(256) k_gather() {
    int lane = threadIdx.x & 31;
    int wid  = threadIdx.x >> 5;
    int v    = blockIdx.x * GATHER_WARPS + wid;

    float nsum = 0.0f;
    if (v < Vv) {
        const __half2* vt2 = (const __half2*)g_vT;   // per-vertex stride 96 half2
        int s = g_rowptr[v];
        int e = g_rowptr[v + 1];
        int n2 = (e - s) >> 1;                        // deg always even
        const int2* adj2 = (const int2*)(g_adj + s);  // s even -> 8B aligned

        __half2 sx = __float2half2_rn(0.0f);
        __half2 sy = __float2half2_rn(0.0f);
        __half2 sz = __float2half2_rn(0.0f);
        for (int t = 0; t < n2; t++) {
            int2 uu = __ldg(&adj2[t]);                // warp-uniform broadcast
            const __half2* p0 = vt2 + (size_t)uu.x * 96;
            const __half2* p1 = vt2 + (size_t)uu.y * 96;
            __half2 x0 = __ldg(&p0[lane]);
            __half2 y0 = __ldg(&p0[32 + lane]);
            __half2 z0 = __ldg(&p0[64 + lane]);
            __half2 x1 = __ldg(&p1[lane]);
            __half2 y1 = __ldg(&p1[32 + lane]);
            __half2 z1 = __ldg(&p1[64 + lane]);
            sx = __hadd2(sx, __hadd2(x0, x1));
            sy = __hadd2(sy, __hadd2(y0, y1));
            sz = __hadd2(sz, __hadd2(z0, z1));
        }

        float2 ax = __half22float2(sx);
        float2 ay = __half22float2(sy);
        float2 az = __half22float2(sz);

        const __half2* pc = vt2 + (size_t)v * 96;
        float2 cx = __half22float2(pc[lane]);
        float2 cy = __half22float2(pc[32 + lane]);
        float2 cz = __half22float2(pc[64 + lane]);
        float invd = 1.0f / fmaxf((float)(e - s), 1.0f);

        float dx0 = cx.x - ax.x * invd, dy0 = cy.x - ay.x * invd, dz0 = cz.x - az.x * invd;
        float dx1 = cx.y - ax.y * invd, dy1 = cy.y - ay.y * invd, dz1 = cz.y - az.y * invd;
        nsum = sqrtf(dx0 * dx0 + dy0 * dy0 + dz0 * dz0)
             + sqrtf(dx1 * dx1 + dy1 * dy1 + dz1 * dz1);
    }

    // warp reduce
    #pragma unroll
    for (int off = 16; off > 0; off >>= 1)
        nsum += __shfl_xor_sync(0xFFFFFFFFu, nsum, off);

    __shared__ float warpsum[GATHER_WARPS];
    if (lane == 0) warpsum[wid] = nsum;
    __syncthreads();
    if (wid == 0) {
        float bsum = (lane < GATHER_WARPS) ? warpsum[lane] : 0.0f;
        #pragma unroll
        for (int off = 4; off > 0; off >>= 1)
            bsum += __shfl_xor_sync(0xFFFFFFFFu, bsum, off);
        if (lane == 0) atomicAdd(&g_accum, bsum);
    }
}

// -------- 7) finalize --------
__global__ void k_finalize(float* __restrict__ out) {
    out[0] = g_accum * (1.0f / ((float)Bb * (float)Vv));
}

extern "C" void kernel_launch(void* const* d_in, const int* in_sizes, int n_in,
                              void* d_out, int out_size) {
    const float* verts   = (const float*)d_in[0];   // (64, 100000, 3) f32
    const int*   faces_w = (const int*)d_in[1];     // (200000, 3) int32 OR int64 (detected)
    float* out = (float*)d_out;

    (void)in_sizes; (void)n_in; (void)out_size;

    k_init<<<(Vv + 255) / 256, 256>>>(faces_w);
    k_count_tp<<<COUNT_NB + TP_SPLIT, 256>>>(faces_w, verts);
    k_scan1<<<SCAN_NB, SCAN_BS>>>();
    k_scan3<<<(Vv + 255) / 256, 256>>>();
    k_fill_tp<<<FILL_NB + (TP_NB - TP_SPLIT), 256>>>(faces_w, verts);
    k_gather<<<(Vv + GATHER_WARPS - 1) / GATHER_WARPS, 256>>>();
    k_finalize<<<1, 1>>>(out);
}

// round 13
// speedup vs baseline: 1.0095x; 1.0095x over previous
#include <cuda_runtime.h>
#include <cuda_fp16.h>
#include <math.h>
#include <cstdint>

// Problem constants (fixed shapes)
#define Bb 64
#define Vv 100000
#define Ff 200000
#define Ee (6 * Ff)          // 1,200,000 adjacency entries (always even per vertex)
#define VT_STRIDE 192        // per-vertex halves: 3 comps * 64 batches (= 48 uint2)

// -------- device scratch (static; no allocations allowed) --------
__device__ int    g_deg[Vv];
__device__ int    g_rowptr[Vv + 1];
__device__ int    g_cursor[Vv];
__device__ __align__(8) int g_adj[Ee];
__device__ __align__(16) __half g_vT[(size_t)Vv * VT_STRIDE];   // 38.4 MB, layout [v][c][b] fp16
__device__ int    g_blocksums[256];
__device__ float  g_accum;
__device__ int    g_faces64;   // 1 if faces buffer is int64, 0 if int32

__device__ __forceinline__ __half2 u2h(uint32_t u) { return *reinterpret_cast<__half2*>(&u); }
__device__ __forceinline__ uint32_t h2u(__half2 h) { return *reinterpret_cast<uint32_t*>(&h); }

// -------- 1) init degrees + detect faces dtype + clear accum --------
__global__ void k_init(const int* __restrict__ faces_w) {
    int idx = blockIdx.x * blockDim.x + threadIdx.x;
    if (idx < Vv) g_deg[idx] = 0;
    if (idx == 0) {
        int nz = 0;
        #pragma unroll
        for (int t = 0; t < 64; t++) nz |= faces_w[2 * t + 1];
        g_faces64 = (nz == 0) ? 1 : 0;
        g_accum = 0.0f;
    }
}

__device__ __forceinline__ void load_face(const int* __restrict__ fw, int f, int w64,
                                          int& i, int& j, int& k) {
    if (w64) {
        i = fw[6 * f + 0];
        j = fw[6 * f + 2];
        k = fw[6 * f + 4];
    } else {
        i = fw[3 * f + 0];
        j = fw[3 * f + 1];
        k = fw[3 * f + 2];
    }
}

// -------- 2) degree count (pure; keeps scan1 dependency cheap) --------
__global__ void k_count(const int* __restrict__ faces_w) {
    int f = blockIdx.x * blockDim.x + threadIdx.x;
    if (f >= Ff) return;
    int w64 = g_faces64;
    int i, j, k;
    load_face(faces_w, f, w64, i, j, k);
    atomicAdd(&g_deg[i], 2);
    atomicAdd(&g_deg[j], 2);
    atomicAdd(&g_deg[k], 2);
}

// -------- 3) scan, level 1 (512-wide blocks, warp shuffles) --------
#define SCAN_BS 512
#define SCAN_NB ((Vv + SCAN_BS - 1) / SCAN_BS)   // 196

__global__ void k_scan1() {
    __shared__ int wsum[16];
    int tid = threadIdx.x, lane = tid & 31, w = tid >> 5;
    int gid = blockIdx.x * SCAN_BS + tid;
    int val = (gid < Vv) ? g_deg[gid] : 0;
    int x = val;
    #pragma unroll
    for (int off = 1; off < 32; off <<= 1) {
        int y = __shfl_up_sync(0xFFFFFFFFu, x, off);
        if (lane >= off) x += y;
    }
    if (lane == 31) wsum[w] = x;
    __syncthreads();
    if (w == 0) {
        int s = (lane < 16) ? wsum[lane] : 0;
        #pragma unroll
        for (int off = 1; off < 16; off <<= 1) {
            int y = __shfl_up_sync(0xFFFFFFFFu, s, off);
            if (lane >= off) s += y;
        }
        if (lane < 16) wsum[lane] = s;
    }
    __syncthreads();
    int base = (w > 0) ? wsum[w - 1] : 0;
    int incl = base + x;
    if (gid < Vv) g_rowptr[gid] = incl - val;        // exclusive within block
    if (tid == SCAN_BS - 1) g_blocksums[blockIdx.x] = incl;
}

// -------- 3b) scan finalize --------
__global__ void k_scan3() {
    __shared__ int spre[256];   // exclusive prefix of blocksums
    __shared__ int wsum[8];
    int tid = threadIdx.x, lane = tid & 31, w = tid >> 5;   // 256 threads
    int val = (tid < SCAN_NB) ? g_blocksums[tid] : 0;
    int x = val;
    #pragma unroll
    for (int off = 1; off < 32; off <<= 1) {
        int y = __shfl_up_sync(0xFFFFFFFFu, x, off);
        if (lane >= off) x += y;
    }
    if (lane == 31) wsum[w] = x;
    __syncthreads();
    if (w == 0) {
        int s = (lane < 8) ? wsum[lane] : 0;
        #pragma unroll
        for (int off = 1; off < 8; off <<= 1) {
            int y = __shfl_up_sync(0xFFFFFFFFu, s, off);
            if (lane >= off) s += y;
        }
        if (lane < 8) wsum[lane] = s;
    }
    __syncthreads();
    int base = (w > 0) ? wsum[w - 1] : 0;
    spre[tid] = base + x - val;                       // exclusive blocksum prefix
    __syncthreads();

    int gid = blockIdx.x * blockDim.x + tid;
    if (gid < Vv) {
        int r = g_rowptr[gid] + spre[gid / SCAN_BS];
        g_rowptr[gid] = r;
        g_cursor[gid] = r;
    }
    if (gid == 0) g_rowptr[Vv] = Ee;
}

// -------- 4+5) fused CSR fill + transpose (heterogeneous grid, R9 structure) --------
#define FILL_NB ((Ff + 255) / 256)          // 782
#define TP_VT 32
#define TP_NB (Vv / TP_VT)                  // 3125

__global__ void __launch_bounds__(256) k_fill_transpose(const int* __restrict__ faces_w,
                                                        const float* __restrict__ verts) {
    __shared__ float sh[TP_VT * 3 * 65];    // used by transpose blocks only
    if (blockIdx.x < FILL_NB) {
        int f = blockIdx.x * 256 + threadIdx.x;
        if (f >= Ff) return;
        int w64 = g_faces64;
        int i, j, k;
        load_face(faces_w, f, w64, i, j, k);
        int p;
        p = atomicAdd(&g_cursor[i], 2); g_adj[p] = j; g_adj[p + 1] = k;
        p = atomicAdd(&g_cursor[j], 2); g_adj[p] = i; g_adj[p + 1] = k;
        p = atomicAdd(&g_cursor[k], 2); g_adj[p] = j; g_adj[p + 1] = i;
    } else {
        int t = threadIdx.x;                     // 256 threads
        int v0 = (int)(blockIdx.x - FILL_NB) * TP_VT;

        #pragma unroll
        for (int it = 0; it < 24; it++) {
            int l = it * 256 + t;
            int b = l / 96;
            int rem = l - b * 96;
            float val = verts[(size_t)b * (Vv * 3) + (size_t)v0 * 3 + rem];
            sh[rem * 65 + b] = val;
        }
        __syncthreads();

        __half2* out = (__half2*)(g_vT + (size_t)v0 * VT_STRIDE);
        #pragma unroll
        for (int it = 0; it < 12; it++) {
            int o = it * 256 + t;              // half2 index within tile
            int v = o / 96;
            int r = o - v * 96;
            int c = r >> 5;                    // component
            int bp = r & 31;                   // batch pair
            float f0 = sh[(v * 3 + c) * 65 + 2 * bp];
            float f1 = sh[(v * 3 + c) * 65 + 2 * bp + 1];
            out[o] = __floats2half2_rn(f0, f1);
        }
    }
}

// -------- 6) gather + norm + reduce (widened loads) --------
// Row = 48 uint2: q 0..15 = x (batches 4q..4q+3), 16..31 = y, 32..47 = z.
// Per 2-neighbor iter: adj int2 + 2 full-warp uint2 loads (x+y of each
// neighbor) + 1 split load (lanes<16: n0's z, lanes>=16: n1's z) = 4 LDGs.
// fp16 accumulation (HADD2) as in R9; z halves combined via shfl_xor(16).
#define GATHER_WARPS 8
__global__ void __launch_bounds__(256) k_gather() {
    int lane = threadIdx.x & 31;
    int wid  = threadIdx.x >> 5;
    int v    = blockIdx.x * GATHER_WARPS + wid;

    float nsum = 0.0f;
    if (v < Vv) {
        const uint2* vt = (const uint2*)g_vT;        // 48 uint2 per vertex
        int s = g_rowptr[v];
        int e = g_rowptr[v + 1];
        int n2 = (e - s) >> 1;                        // deg always even
        const int2* adj2 = (const int2*)(g_adj + s);  // s even -> 8B aligned
        int lz = lane & 15;

        __half2 aA0 = __float2half2_rn(0.0f);         // x (lanes<16) / y (lanes>=16), batches 4l..4l+1
        __half2 aA1 = __float2half2_rn(0.0f);         //   "                        , batches 4l+2..4l+3
        __half2 aZ0 = __float2half2_rn(0.0f);         // z partial (even/odd neighbors per half-warp)
        __half2 aZ1 = __float2half2_rn(0.0f);

        for (int t = 0; t < n2; t++) {
            int2 uu = __ldg(&adj2[t]);                // warp-uniform broadcast
            const uint2* r0 = vt + (size_t)uu.x * 48;
            const uint2* r1 = vt + (size_t)uu.y * 48;
            uint2 A0 = __ldg(&r0[lane]);
            uint2 A1 = __ldg(&r1[lane]);
            const uint2* rb = (lane < 16) ? r0 : r1;
            uint2 B = __ldg(&rb[32 + lz]);
            aA0 = __hadd2(aA0, __hadd2(u2h(A0.x), u2h(A1.x)));
            aA1 = __hadd2(aA1, __hadd2(u2h(A0.y), u2h(A1.y)));
            aZ0 = __hadd2(aZ0, u2h(B.x));
            aZ1 = __hadd2(aZ1, u2h(B.y));
        }

        // combine z across half-warps (lanes<16 hold even-neighbor sums, >=16 odd)
        aZ0 = __hadd2(aZ0, u2h(__shfl_xor_sync(0xFFFFFFFFu, h2u(aZ0), 16)));
        aZ1 = __hadd2(aZ1, u2h(__shfl_xor_sync(0xFFFFFFFFu, h2u(aZ1), 16)));

        // center vertex, same layout
        const uint2* rc = vt + (size_t)v * 48;
        uint2 CA = __ldg(&rc[lane]);                  // x (lanes<16) / y (lanes>=16)
        uint2 CB = __ldg(&rc[32 + lz]);               // z (duplicated across half-warps)

        // bring y data (sums + center) from lane lz+16 down to lanes 0..15
        uint32_t yS0 = __shfl_sync(0xFFFFFFFFu, h2u(aA0), lz + 16);
        uint32_t yS1 = __shfl_sync(0xFFFFFFFFu, h2u(aA1), lz + 16);
        uint32_t yC0 = __shfl_sync(0xFFFFFFFFu, CA.x, lz + 16);
        uint32_t yC1 = __shfl_sync(0xFFFFFFFFu, CA.y, lz + 16);

        if (lane < 16) {
            float invd = 1.0f / fmaxf((float)(e - s), 1.0f);
            float2 sx01 = __half22float2(aA0),      sx23 = __half22float2(aA1);
            float2 sy01 = __half22float2(u2h(yS0)), sy23 = __half22float2(u2h(yS1));
            float2 sz01 = __half22float2(aZ0),      sz23 = __half22float2(aZ1);
            float2 cx01 = __half22float2(u2h(CA.x)), cx23 = __half22float2(u2h(CA.y));
            float2 cy01 = __half22float2(u2h(yC0)),  cy23 = __half22float2(u2h(yC1));
            float2 cz01 = __half22float2(u2h(CB.x)), cz23 = __half22float2(u2h(CB.y));

            float dx, dy, dz;
            dx = cx01.x - sx01.x * invd; dy = cy01.x - sy01.x * invd; dz = cz01.x - sz01.x * invd;
            nsum += sqrtf(dx * dx + dy * dy + dz * dz);
            dx = cx01.y - sx01.y * invd; dy = cy01.y - sy01.y * invd; dz = cz01.y - sz01.y * invd;
            nsum += sqrtf(dx * dx + dy * dy + dz * dz);
            dx = cx23.x - sx23.x * invd; dy = cy23.x - sy23.x * invd; dz = cz23.x - sz23.x * invd;
            nsum += sqrtf(dx * dx + dy * dy + dz * dz);
            dx = cx23.y - sx23.y * invd; dy = cy23.y - sy23.y * invd; dz = cz23.y - sz23.y * invd;
            nsum += sqrtf(dx * dx + dy * dy + dz * dz);
        }
    }

    // warp reduce
    #pragma unroll
    for (int off = 16; off > 0; off >>= 1)
        nsum += __shfl_xor_sync(0xFFFFFFFFu, nsum, off);

    __shared__ float warpsum[GATHER_WARPS];
    if (lane == 0) warpsum[wid] = nsum;
    __syncthreads();
    if (wid == 0) {
        float bsum = (lane < GATHER_WARPS) ? warpsum[lane] : 0.0f;
        #pragma unroll
        for (int off = 4; off > 0; off >>= 1)
            bsum += __shfl_xor_sync(0xFFFFFFFFu, bsum, off);
        if (lane == 0) atomicAdd(&g_accum, bsum);
    }
}

// -------- 7) finalize --------
__global__ void k_finalize(float* __restrict__ out) {
    out[0] = g_accum * (1.0f / ((float)Bb * (float)Vv));
}

extern "C" void kernel_launch(void* const* d_in, const int* in_sizes, int n_in,
                              void* d_out, int out_size) {
    const float* verts   = (const float*)d_in[0];   // (64, 100000, 3) f32
    const int*   faces_w = (const int*)d_in[1];     // (200000, 3) int32 OR int64 (detected)
    float* out = (float*)d_out;

    (void)in_sizes; (void)n_in; (void)out_size;

    k_init<<<(Vv + 255) / 256, 256>>>(faces_w);
    k_count<<<(Ff + 255) / 256, 256>>>(faces_w);
    k_scan1<<<SCAN_NB, SCAN_BS>>>();
    k_scan3<<<(Vv + 255) / 256, 256>>>();
    k_fill_transpose<<<FILL_NB + TP_NB, 256>>>(faces_w, verts);
    k_gather<<<(Vv + GATHER_WARPS - 1) / GATHER_WARPS, 256>>>();
    k_finalize<<<1, 1>>>(out);
}

// round 17
// speedup vs baseline: 1.1617x; 1.1508x over previous
#include <cuda_runtime.h>
#include <cuda_fp16.h>
#include <math.h>
#include <cstdint>

// Problem constants (fixed shapes)
#define Bb 64
#define Vv 100000
#define Ff 200000
#define Ee (6 * Ff)          // 1,200,000 adjacency entries (always even per vertex)
#define VT_STRIDE 192        // per-vertex halves: 3 comps * 64 batches

#define SCAN_BS 512
#define SCAN_NB ((Vv + SCAN_BS - 1) / SCAN_BS)   // 196

// -------- zero-initialized scratch: ONE memset covers deg + scan state + accum --------
// layout: [0,Vv) = deg, [Vv,Vv+SCAN_NB) = lookback state, [Vv+SCAN_NB] = accum bits
__device__ int g_zbuf[Vv + SCAN_NB + 1];
#define g_deg  g_zbuf
#define g_part (g_zbuf + Vv)
#define g_accum_ptr ((float*)(g_zbuf + Vv + SCAN_NB))

__device__ int    g_rowptr[Vv + 1];
__device__ int    g_cursor[Vv];
__device__ __align__(8) int g_adj[Ee];
__device__ __align__(16) __half g_vT[(size_t)Vv * VT_STRIDE];   // 38.4 MB, [v][c][b] fp16

// lookback states (sums <= 1.2M < 2^29)
#define ST_AGG  (1 << 29)
#define ST_INC  (2 << 29)
#define ST_MASK (3 << 29)

// per-block faces-dtype probe: int64 ids < 2^31 -> all odd words 0.
// int32 random ids: P(16 odd words all zero) ~ (1e-5)^16 ~ 0.
__device__ __forceinline__ int detect_w64(const int* __restrict__ fw) {
    int nz = 0;
    #pragma unroll
    for (int t = 0; t < 16; t++) nz |= fw[2 * t + 1];
    return (nz == 0) ? 1 : 0;
}

__device__ __forceinline__ void load_face(const int* __restrict__ fw, int f, int w64,
                                          int& i, int& j, int& k) {
    if (w64) {
        i = fw[6 * f + 0];
        j = fw[6 * f + 2];
        k = fw[6 * f + 4];
    } else {
        i = fw[3 * f + 0];
        j = fw[3 * f + 1];
        k = fw[3 * f + 2];
    }
}

// -------- 1) degree count (per-block dtype probe folded in) --------
__global__ void k_count(const int* __restrict__ faces_w) {
    __shared__ int s_w64;
    if (threadIdx.x == 0) s_w64 = detect_w64(faces_w);
    __syncthreads();
    int f = blockIdx.x * blockDim.x + threadIdx.x;
    if (f >= Ff) return;
    int i, j, k;
    load_face(faces_w, f, s_w64, i, j, k);
    atomicAdd(&g_deg[i], 2);
    atomicAdd(&g_deg[j], 2);
    atomicAdd(&g_deg[k], 2);
}

// -------- 2) single-pass exclusive scan (decoupled lookback) -> rowptr + cursor --------
__global__ void __launch_bounds__(SCAN_BS) k_scan() {
    __shared__ int wsum[16];
    __shared__ int s_base;
    int tid = threadIdx.x, lane = tid & 31, w = tid >> 5;
    int bid = blockIdx.x;
    int gid = bid * SCAN_BS + tid;
    int val = (gid < Vv) ? g_deg[gid] : 0;
    int x = val;
    #pragma unroll
    for (int off = 1; off < 32; off <<= 1) {
        int y = __shfl_up_sync(0xFFFFFFFFu, x, off);
        if (lane >= off) x += y;
    }
    if (lane == 31) wsum[w] = x;
    __syncthreads();
    if (w == 0) {
        int s = (lane < 16) ? wsum[lane] : 0;
        #pragma unroll
        for (int off = 1; off < 16; off <<= 1) {
            int y = __shfl_up_sync(0xFFFFFFFFu, s, off);
            if (lane >= off) s += y;
        }
        if (lane < 16) wsum[lane] = s;
    }
    __syncthreads();
    int base = (w > 0) ? wsum[w - 1] : 0;
    int incl = base + x;               // inclusive within block
    int btotal = wsum[15];             // block total

    if (w == 0) {
        if (bid == 0) {
            if (lane == 0) {
                atomicExch(&g_part[0], ST_INC | btotal);
                s_base = 0;
            }
        } else {
            if (lane == 0) atomicExch(&g_part[bid], ST_AGG | btotal);
            int running = 0;
            int pos = bid - 1;
            while (true) {
                int idx = pos - lane;
                int v = 0;
                if (idx >= 0) {
                    do { v = atomicAdd(&g_part[idx], 0); } while ((v & ST_MASK) == 0);
                }
                unsigned incmask = __ballot_sync(0xFFFFFFFFu,
                                                 idx >= 0 && (v & ST_MASK) == ST_INC);
                if (incmask) {
                    int leader = __ffs(incmask) - 1;   // nearest predecessor with inclusive
                    int contrib = (lane <= leader) ? (v & ~ST_MASK) : 0;
                    #pragma unroll
                    for (int o = 16; o > 0; o >>= 1)
                        contrib += __shfl_xor_sync(0xFFFFFFFFu, contrib, o);
                    running += contrib;
                    break;
                } else {
                    int contrib = (idx >= 0) ? (v & ~ST_MASK) : 0;
                    #pragma unroll
                    for (int o = 16; o > 0; o >>= 1)
                        contrib += __shfl_xor_sync(0xFFFFFFFFu, contrib, o);
                    running += contrib;
                    pos -= 32;
                }
            }
            if (lane == 0) {
                atomicExch(&g_part[bid], ST_INC | (running + btotal));
                s_base = running;
            }
        }
    }
    __syncthreads();
    if (gid < Vv) {
        int r = s_base + incl - val;   // global exclusive prefix
        g_rowptr[gid] = r;
        g_cursor[gid] = r;
    }
    if (gid == 0) g_rowptr[Vv] = Ee;
}

// -------- 3) fused CSR fill + transpose (heterogeneous grid, R9 structure) --------
#define FILL_NB ((Ff + 255) / 256)          // 782
#define TP_VT 32
#define TP_NB (Vv / TP_VT)                  // 3125

__global__ void __launch_bounds__(256) k_fill_transpose(const int* __restrict__ faces_w,
                                                        const float* __restrict__ verts) {
    __shared__ float sh[TP_VT * 3 * 65];    // transpose blocks only
    __shared__ int s_w64;
    if (blockIdx.x < FILL_NB) {
        if (threadIdx.x == 0) s_w64 = detect_w64(faces_w);
        __syncthreads();
        int f = blockIdx.x * 256 + threadIdx.x;
        if (f >= Ff) return;
        int i, j, k;
        load_face(faces_w, f, s_w64, i, j, k);
        int p;
        p = atomicAdd(&g_cursor[i], 2); g_adj[p] = j; g_adj[p + 1] = k;
        p = atomicAdd(&g_cursor[j], 2); g_adj[p] = i; g_adj[p + 1] = k;
        p = atomicAdd(&g_cursor[k], 2); g_adj[p] = j; g_adj[p + 1] = i;
    } else {
        int t = threadIdx.x;                     // 256 threads
        int v0 = (int)(blockIdx.x - FILL_NB) * TP_VT;

        #pragma unroll
        for (int it = 0; it < 24; it++) {
            int l = it * 256 + t;
            int b = l / 96;
            int rem = l - b * 96;
            float val = verts[(size_t)b * (Vv * 3) + (size_t)v0 * 3 + rem];
            sh[rem * 65 + b] = val;
        }
        __syncthreads();

        __half2* out = (__half2*)(g_vT + (size_t)v0 * VT_STRIDE);
        #pragma unroll
        for (int it = 0; it < 12; it++) {
            int o = it * 256 + t;              // half2 index within tile
            int v = o / 96;
            int r = o - v * 96;
            int c = r >> 5;                    // component
            int bp = r & 31;                   // batch pair
            float f0 = sh[(v * 3 + c) * 65 + 2 * bp];
            float f1 = sh[(v * 3 + c) * 65 + 2 * bp + 1];
            out[o] = __floats2half2_rn(f0, f1);
        }
    }
}

// -------- 4) gather + norm + reduce (EXACT R9 winner: do not touch) --------
#define GATHER_WARPS 8
__global__ void __launch_bounds__(256) k_gather() {
    int lane = threadIdx.x & 31;
    int wid  = threadIdx.x >> 5;
    int v    = blockIdx.x * GATHER_WARPS + wid;

    float nsum = 0.0f;
    if (v < Vv) {
        const __half2* vt2 = (const __half2*)g_vT;   // per-vertex stride 96 half2
        int s = g_rowptr[v];
        int e = g_rowptr[v + 1];
        int n2 = (e - s) >> 1;                        // deg always even
        const int2* adj2 = (const int2*)(g_adj + s);  // s even -> 8B aligned

        __half2 sx = __float2half2_rn(0.0f);
        __half2 sy = __float2half2_rn(0.0f);
        __half2 sz = __float2half2_rn(0.0f);
        for (int t = 0; t < n2; t++) {
            int2 uu = __ldg(&adj2[t]);                // warp-uniform broadcast
            const __half2* p0 = vt2 + (size_t)uu.x * 96;
            const __half2* p1 = vt2 + (size_t)uu.y * 96;
            __half2 x0 = __ldg(&p0[lane]);
            __half2 y0 = __ldg(&p0[32 + lane]);
            __half2 z0 = __ldg(&p0[64 + lane]);
            __half2 x1 = __ldg(&p1[lane]);
            __half2 y1 = __ldg(&p1[32 + lane]);
            __half2 z1 = __ldg(&p1[64 + lane]);
            sx = __hadd2(sx, __hadd2(x0, x1));
            sy = __hadd2(sy, __hadd2(y0, y1));
            sz = __hadd2(sz, __hadd2(z0, z1));
        }

        float2 ax = __half22float2(sx);
        float2 ay = __half22float2(sy);
        float2 az = __half22float2(sz);

        const __half2* pc = vt2 + (size_t)v * 96;
        float2 cx = __half22float2(pc[lane]);
        float2 cy = __half22float2(pc[32 + lane]);
        float2 cz = __half22float2(pc[64 + lane]);
        float invd = 1.0f / fmaxf((float)(e - s), 1.0f);

        float dx0 = cx.x - ax.x * invd, dy0 = cy.x - ay.x * invd, dz0 = cz.x - az.x * invd;
        float dx1 = cx.y - ax.y * invd, dy1 = cy.y - ay.y * invd, dz1 = cz.y - az.y * invd;
        nsum = sqrtf(dx0 * dx0 + dy0 * dy0 + dz0 * dz0)
             + sqrtf(dx1 * dx1 + dy1 * dy1 + dz1 * dz1);
    }

    // warp reduce
    #pragma unroll
    for (int off = 16; off > 0; off >>= 1)
        nsum += __shfl_xor_sync(0xFFFFFFFFu, nsum, off);

    __shared__ float warpsum[GATHER_WARPS];
    if (lane == 0) warpsum[wid] = nsum;
    __syncthreads();
    if (wid == 0) {
        float bsum = (lane < GATHER_WARPS) ? warpsum[lane] : 0.0f;
        #pragma unroll
        for (int off = 4; off > 0; off >>= 1)
            bsum += __shfl_xor_sync(0xFFFFFFFFu, bsum, off);
        if (lane == 0) atomicAdd(g_accum_ptr, bsum);
    }
}

// -------- 5) finalize --------
__global__ void k_finalize(float* __restrict__ out) {
    out[0] = (*g_accum_ptr) * (1.0f / ((float)Bb * (float)Vv));
}

extern "C" void kernel_launch(void* const* d_in, const int* in_sizes, int n_in,
                              void* d_out, int out_size) {
    const float* verts   = (const float*)d_in[0];   // (64, 100000, 3) f32
    const int*   faces_w = (const int*)d_in[1];     // (200000, 3) int32 OR int64 (detected)
    float* out = (float*)d_out;

    (void)in_sizes; (void)n_in; (void)out_size;

    void* zp = nullptr;
    cudaGetSymbolAddress(&zp, g_zbuf);
    cudaMemsetAsync(zp, 0, sizeof(int) * (Vv + SCAN_NB + 1));

    k_count<<<(Ff + 255) / 256, 256>>>(faces_w);
    k_scan<<<SCAN_NB, SCAN_BS>>>();
    k_fill_transpose<<<FILL_NB + TP_NB, 256>>>(faces_w, verts);
    k_gather<<<(Vv + GATHER_WARPS - 1) / GATHER_WARPS, 256>>>();
    k_finalize<<<1, 1>>>(out);
}